// round 6
// baseline (speedup 1.0000x reference)
#include <cuda_runtime.h>
#include <math.h>

// ---------------------------------------------------------------------------
// LSForward: Born-series scattering, M=4096 pts, 4 wavenumbers (0.5*m), 5 iters.
// R6: revert to R3 math (theta-cache was DRAM-bound: 67MB/iter missed L2 and
// recompute beats the round-trip). New lever: ONE persistent kernel with a
// software grid barrier removes ~12 graph-node launch gaps (~15-20us of the
// 24us non-acc overhead). Acc phase is the verified R3 body unchanged; acc is
// at the 3-reg FFMA roofline (48.6% of ncu's rt=1-normalized peak = ~97%).
// Co-residency for the barrier is guaranteed by __launch_bounds__(128, 8):
// 8 blocks/SM * 148 = 1184 >= 1024 blocks.
// ---------------------------------------------------------------------------

constexpr int M_PTS  = 4096;
constexpr int NDOBS  = 64;
constexpr int NK     = 4;
constexpr int N_ITER = 5;

constexpr int TPB    = 128;                    // threads per block
constexpr int RPT    = 2;                      // rows per thread
constexpr int ROWBLK = 16;                     // row-blocks (256 rows each)
constexpr int JSPLIT = 64;                     // j-partition count
constexpr int JCHUNK = M_PTS / JSPLIT;         // 64 j's per unit
constexpr int GRID   = ROWBLK * JSPLIT;        // 1024 blocks

constexpr float C_G = 0.07957747154594767f;    // 1/(4*pi)

// Scratch (allocation-free: __device__ globals)
__device__ float g_px[M_PTS], g_py[M_PTS], g_pz[M_PTS];
__device__ float g_r2q[M_PTS];                     // 0.25*|p|^2
__device__ float g_vw[M_PTS];                      // 0.5*C_G * V * w (folded)
__device__ float g_p0[NK * 2 * M_PTS];
__device__ float g_p [NK * 2 * M_PTS];
__device__ float g_a [NK * 2 * M_PTS];             // folded matvec input
__device__ float g_part[JSPLIT][NK * 2 * M_PTS];   // deterministic j-partials (8 MB)

// Software grid barrier state
__device__ unsigned g_bar_cnt = 0;
__device__ unsigned g_bar_gen = 0;

__device__ __forceinline__ float fsqrt_approx(float x) {
    float r; asm("sqrt.approx.f32 %0,%1;" : "=f"(r) : "f"(x)); return r;
}

__device__ __forceinline__ void grid_sync() {
    __syncthreads();
    if (threadIdx.x == 0) {
        volatile unsigned* genp = &g_bar_gen;
        unsigned gen = *genp;
        __threadfence();
        unsigned arrived = atomicAdd(&g_bar_cnt, 1u);
        if (arrived == GRID - 1) {
            g_bar_cnt = 0;
            __threadfence();
            *genp = gen + 1;
        } else {
            while (*genp == gen) { __nanosleep(64); }
            __threadfence();
        }
    }
    __syncthreads();
}

// ---------------------------------------------------------------------------
// The whole solver in one persistent kernel.
// ---------------------------------------------------------------------------
__global__ __launch_bounds__(TPB, 8) void k_born(
    const float* __restrict__ V,
    const float* __restrict__ obs,
    const float* __restrict__ pts,
    const float* __restrict__ w,
    float* __restrict__ out)
{
    __shared__ alignas(16) float sj[JCHUNK][12];   // px,py,pz,r2q, ar0,ai0..ar3,ai3
    __shared__ float sred[32][4];                  // update/far reduction scratch

    int t  = threadIdx.x;
    int b  = blockIdx.x;
    int bx = b & (ROWBLK - 1);                     // row-block
    int by = b >> 4;                               // j-chunk

    // ======================= init phase (blocks 0..31) =====================
    if (b < M_PTS / TPB) {
        int i = b * TPB + t;
        float x = pts[3 * i], y = pts[3 * i + 1], z = pts[3 * i + 2];
        g_px[i] = x; g_py[i] = y; g_pz[i] = z;
        g_r2q[i] = 0.25f * (x * x + y * y + z * z);
        float vw = 0.5f * C_G * V[i] * w[i];
        g_vw[i] = vw;
#pragma unroll
        for (int m = 0; m < NK; m++) {
            float kv = 0.5f * (float)(m + 1);
            float s, c;
            sincosf(kv * z, &s, &c);               // accurate; one-time cost
            g_p0[m * 2 * M_PTS + i]          = c;
            g_p0[m * 2 * M_PTS + M_PTS + i]  = s;
            g_p [m * 2 * M_PTS + i]          = c;
            g_p [m * 2 * M_PTS + M_PTS + i]  = s;
            g_a [m * 2 * M_PTS + i]          = vw * c;
            g_a [m * 2 * M_PTS + M_PTS + i]  = vw * s;
        }
    }
    grid_sync();

    // ======================= Born iterations ===============================
    for (int it = 0; it < N_ITER; it++) {
        // ---- phase A: matvec partials (verified R3 body) ----
        {
            int j0 = by * JCHUNK;
            if (t < JCHUNK) {
                int j = j0 + t;
                sj[t][0] = g_px[j];
                sj[t][1] = g_py[j];
                sj[t][2] = g_pz[j];
                sj[t][3] = g_r2q[j];
#pragma unroll
                for (int m = 0; m < NK; m++) {
                    sj[t][4 + 2 * m] = g_a[m * 2 * M_PTS + j];
                    sj[t][5 + 2 * m] = g_a[m * 2 * M_PTS + M_PTS + j];
                }
            }
            __syncthreads();

            int rbase = bx * (TPB * RPT) + t;
            float pix[RPT], piy[RPT], piz[RPT], r2i[RPT];
#pragma unroll
            for (int r = 0; r < RPT; r++) {
                int row = rbase + r * TPB;
                pix[r] = g_px[row]; piy[r] = g_py[row];
                piz[r] = g_pz[row]; r2i[r] = g_r2q[row];
            }

            float accr[RPT][NK], acci[RPT][NK];
#pragma unroll
            for (int r = 0; r < RPT; r++)
#pragma unroll
                for (int m = 0; m < NK; m++) { accr[r][m] = 0.f; acci[r][m] = 0.f; }

#pragma unroll 2
            for (int jj = 0; jj < JCHUNK; jj++) {
                float4 P  = *reinterpret_cast<const float4*>(&sj[jj][0]);
                float4 A0 = *reinterpret_cast<const float4*>(&sj[jj][4]);
                float4 A1 = *reinterpret_cast<const float4*>(&sj[jj][8]);
                int jg = j0 + jj;
#pragma unroll
                for (int r = 0; r < RPT; r++) {
                    int row = rbase + r * TPB;
                    float dot = fmaf(pix[r], P.x, fmaf(piy[r], P.y, piz[r] * P.z));
                    float e   = fmaf(-0.5f, dot, r2i[r] + P.w);   // 0.25*d2
                    e = fmaxf(e, 2.5e-13f);
                    float th  = fsqrt_approx(e);                  // 0.5*D
                    float sc  = rsqrtf(e);                        // 2/D (scale in a)
                    sc = (row == jg) ? 0.f : sc;
                    float s1, c1;
                    __sincosf(th, &s1, &c1);
                    float tc  = __fmul_rn(c1, 2.0f);
                    float g1r = sc * c1,             g1i = sc * s1;
                    float g2r = fmaf(tc, g1r, -sc);  float g2i = tc * g1i;
                    float g3r = fmaf(tc, g2r, -g1r); float g3i = fmaf(tc, g2i, -g1i);
                    float g4r = fmaf(tc, g3r, -g2r); float g4i = fmaf(tc, g3i, -g2i);
                    accr[r][0] = fmaf(g1r, A0.x, fmaf(-g1i, A0.y, accr[r][0]));
                    acci[r][0] = fmaf(g1r, A0.y, fmaf( g1i, A0.x, acci[r][0]));
                    accr[r][1] = fmaf(g2r, A0.z, fmaf(-g2i, A0.w, accr[r][1]));
                    acci[r][1] = fmaf(g2r, A0.w, fmaf( g2i, A0.z, acci[r][1]));
                    accr[r][2] = fmaf(g3r, A1.x, fmaf(-g3i, A1.y, accr[r][2]));
                    acci[r][2] = fmaf(g3r, A1.y, fmaf( g3i, A1.x, acci[r][2]));
                    accr[r][3] = fmaf(g4r, A1.z, fmaf(-g4i, A1.w, accr[r][3]));
                    acci[r][3] = fmaf(g4r, A1.w, fmaf( g4i, A1.z, acci[r][3]));
                }
            }

            float* part = g_part[by];
#pragma unroll
            for (int r = 0; r < RPT; r++) {
                int row = rbase + r * TPB;
#pragma unroll
                for (int m = 0; m < NK; m++) {
                    part[m * 2 * M_PTS + row]         = accr[r][m];
                    part[m * 2 * M_PTS + M_PTS + row] = acci[r][m];
                }
            }
        }
        grid_sync();

        // ---- phase B: deterministic reduction + Born update ----
        // block b owns outputs e in [32b, 32b+32); 4 threads per output,
        // fixed combine order for determinism.
        {
            int tq = t & 3;                    // quarter of the js range
            int eo = t >> 2;                   // 0..31
            int e  = b * 32 + eo;
            float s = 0.f;
            int jsb = tq * 16;
#pragma unroll 4
            for (int js = 0; js < 16; js++) s += g_part[jsb + js][e];
            sred[eo][tq] = s;
            __syncthreads();
            if (t < 32) {
                int e2 = b * 32 + t;
                float sum = ((sred[t][0] + sred[t][1]) + sred[t][2]) + sred[t][3];
                float pv = g_p0[e2] + sum;
                g_p[e2] = pv;
                g_a[e2] = g_vw[e2 & (M_PTS - 1)] * pv;
            }
            __syncthreads();                   // sred reused next iteration
        }
        grid_sync();
    }

    // ======================= far-field (blocks 0..63) ======================
    if (b < NDOBS) {
        int d = b;
        float ox = obs[3 * d], oy = obs[3 * d + 1], oz = obs[3 * d + 2];

        float fr[NK] = {0.f, 0.f, 0.f, 0.f};
        float fi[NK] = {0.f, 0.f, 0.f, 0.f};

        for (int j = t; j < M_PTS; j += TPB) {
            float q = fmaf(g_px[j], ox, fmaf(g_py[j], oy, g_pz[j] * oz));
            float s1, c1;
            __sincosf(0.5f * q, &s1, &c1);
            float tc = c1 + c1;
            float cm[NK], sm[NK];
            cm[0] = c1;                      sm[0] = s1;
            cm[1] = fmaf(tc, c1, -1.f);      sm[1] = tc * s1;
            cm[2] = fmaf(tc, cm[1], -cm[0]); sm[2] = fmaf(tc, sm[1], -sm[0]);
            cm[3] = fmaf(tc, cm[2], -cm[1]); sm[3] = fmaf(tc, sm[2], -sm[1]);
            float v = V[j], wj = w[j];
#pragma unroll
            for (int m = 0; m < NK; m++) {
                float pr = g_p[m * 2 * M_PTS + j];
                float pi = g_p[m * 2 * M_PTS + M_PTS + j];
                float zr = v * pr, zi = v * pi;
                float ir = fmaf(zr, cm[m],  zi * sm[m]);   // exp(-ikQ)
                float ii = fmaf(zi, cm[m], -zr * sm[m]);
                fr[m] = fmaf(wj, ir, fr[m]);
                fi[m] = fmaf(wj, ii, fi[m]);
            }
        }

#pragma unroll
        for (int off = 16; off; off >>= 1) {
#pragma unroll
            for (int m = 0; m < NK; m++) {
                fr[m] += __shfl_down_sync(0xffffffffu, fr[m], off);
                fi[m] += __shfl_down_sync(0xffffffffu, fi[m], off);
            }
        }
        int lane = t & 31, wid = t >> 5;
        if (lane == 0) {
#pragma unroll
            for (int m = 0; m < NK; m++) {
                sred[2 * m][wid]     = fr[m];
                sred[2 * m + 1][wid] = fi[m];
            }
        }
        __syncthreads();
        if (t < 8) {
            float s = ((sred[t][0] + sred[t][1]) + sred[t][2]) + sred[t][3];
            int m = t >> 1, c = t & 1;
            out[m * NDOBS * 2 + d * 2 + c] = -C_G * s;
        }
    }
}

// ---------------------------------------------------------------------------
extern "C" void kernel_launch(void* const* d_in, const int* in_sizes, int n_in,
                              void* d_out, int out_size) {
    const float* V   = (const float*)d_in[0];   // [4096]
    const float* obs = (const float*)d_in[1];   // [64,3]
    const float* pts = (const float*)d_in[2];   // [4096,3]
    const float* w   = (const float*)d_in[3];   // [4096]
    float* out = (float*)d_out;                 // [4,64,2]

    k_born<<<GRID, TPB>>>(V, obs, pts, w, out);
}

// round 8
// speedup vs baseline: 1.0784x; 1.0784x over previous
#include <cuda_runtime.h>
#include <math.h>

// ---------------------------------------------------------------------------
// LSForward: Born-series scattering, M=4096 pts, 4 wavenumbers (0.5*m), 5 iters.
// R8: symmetric rotation scheme (R4) RESURRECTED. R4/R7 failed with identical
// rel_err -> common element was the folded -0.5 distance form, which has
// catastrophic cancellation at near-coincident pairs (e=0.25d^2 ~ 1e-7 vs O(1)
// partials; sc=rsqrt(e)~1e4 amplifies). Fix: R3-exact e-form (dot, then ONE
// fused -0.5*dot+r2sum). G_ij=G_ji: each unordered pair computed once,
// accumulated into both rows (45 fma vs 58). PDL keeps launch gaps down
// (proven output-neutral by R4==R7). fdouble_alu proven exact the same way.
// ---------------------------------------------------------------------------

constexpr int M_PTS  = 4096;
constexpr int NDOBS  = 64;
constexpr int NK     = 4;
constexpr int N_ITER = 5;

constexpr int NWR     = 128;                  // warp-rows of 32
constexpr int NCHUNK  = 16;                   // delta-chunks of 4 (deltas 1..64)
constexpr int UNITS_A = NCHUNK + 1;           // + diagonal unit
constexpr int WPB     = 4;                    // warps per block
constexpr int NBLK    = NWR * UNITS_A / WPB;  // 544 blocks

constexpr float C_G = 0.07957747154594767f;   // 1/(4*pi)

// Scratch (allocation-free __device__ globals)
__device__ float g_px[M_PTS], g_py[M_PTS], g_pz[M_PTS];
__device__ float g_r2q[M_PTS];                    // 0.25*|p|^2
__device__ float g_vw[M_PTS];                     // 0.5*C_G * V * w (folded)
__device__ float g_p0[NK * 2 * M_PTS];
__device__ float g_p [NK * 2 * M_PTS];
__device__ float g_a [NK * 2 * M_PTS];            // folded matvec input
__device__ float g_ipart[NWR][NCHUNK][32][8];     // i-side partials (2 MB)
__device__ float g_jpart[NWR][65][32][8];         // j-side partials, idx=delta (8.5 MB)

__device__ __forceinline__ float fsqrt_approx(float x) {
    float r; asm("sqrt.approx.f32 %0,%1;" : "=f"(r) : "f"(x)); return r;
}
__device__ __forceinline__ float fdouble_alu(float x) {
    // exact 2*x for normal floats via exponent increment (alu pipe)
    return __int_as_float(__float_as_int(x) + 0x00800000);
}
__device__ __forceinline__ void pdl_wait() {
#if __CUDA_ARCH__ >= 900
    cudaGridDependencySynchronize();
#endif
}

// ---------------------------------------------------------------------------
__global__ void k_init(const float* __restrict__ V,
                       const float* __restrict__ pts,
                       const float* __restrict__ w) {
    int i = blockIdx.x * blockDim.x + threadIdx.x;
    if (i >= M_PTS) return;
    float x = pts[3 * i], y = pts[3 * i + 1], z = pts[3 * i + 2];
    g_px[i] = x; g_py[i] = y; g_pz[i] = z;
    g_r2q[i] = 0.25f * (x * x + y * y + z * z);
    float vw = 0.5f * C_G * V[i] * w[i];
    g_vw[i] = vw;
#pragma unroll
    for (int m = 0; m < NK; m++) {
        float kv = 0.5f * (float)(m + 1);
        float s, c;
        sincosf(kv * z, &s, &c);
        g_p0[m * 2 * M_PTS + i]          = c;
        g_p0[m * 2 * M_PTS + M_PTS + i]  = s;
        g_p [m * 2 * M_PTS + i]          = c;
        g_p [m * 2 * M_PTS + M_PTS + i]  = s;
        g_a [m * 2 * M_PTS + i]          = vw * c;
        g_a [m * 2 * M_PTS + M_PTS + i]  = vw * s;
    }
}

// ---------------------------------------------------------------------------
// Symmetric Born matvec. warp-unit = (a, sub); sub<16: 4 off-diag tiles
// delta = 4*sub+1..4*sub+4 (dual-side); sub==16: diagonal tile (single-side).
// e-form matches R3 EXACTLY: dot first, then one fused -0.5*dot + r2sum.
// ---------------------------------------------------------------------------
__global__ __launch_bounds__(128) void k_acc() {
    pdl_wait();

    int warp = blockIdx.x * WPB + (threadIdx.x >> 5);
    int lane = threadIdx.x & 31;
    int a    = warp / UNITS_A;
    int sub  = warp - a * UNITS_A;
    int src  = (lane + 1) & 31;                 // rotation source lane

    // rotating i-context: row i0 = 32a + lane
    int i0 = 32 * a + lane;
    float Rpx = g_px[i0], Rpy = g_py[i0], Rpz = g_pz[i0], Rr2 = g_r2q[i0];
    float Rar[NK], Rai[NK];
#pragma unroll
    for (int m = 0; m < NK; m++) {
        Rar[m] = g_a[m * 2 * M_PTS + i0];
        Rai[m] = g_a[m * 2 * M_PTS + M_PTS + i0];
    }

    if (sub < NCHUNK) {
        // ---- dual-side: 4 fixed j-contexts sharing one rotation ----
        float Jpx[4], Jpy[4], Jpz[4], Jr2[4];
        float Jar[4][NK], Jai[4][NK];
        float Jacr[4][NK], Jaci[4][NK];
        int   brow[4]; bool valid[4];
#pragma unroll
        for (int t = 0; t < 4; t++) {
            int d = 4 * sub + 1 + t;
            bool v = (d < 64) || (a < 64);      // delta==64 only for a<64
            int b  = (a + d) & (NWR - 1);
            brow[t] = b; valid[t] = v;
            int j = 32 * b + lane;
            Jpx[t] = v ? g_px[j] : Rpx;
            Jpy[t] = v ? g_py[j] : Rpy;
            Jpz[t] = v ? g_pz[j] : Rpz;
            Jr2[t] = v ? g_r2q[j] : Rr2;
#pragma unroll
            for (int m = 0; m < NK; m++) {
                Jar[t][m] = v ? g_a[m * 2 * M_PTS + j] : 0.f;
                Jai[t][m] = v ? g_a[m * 2 * M_PTS + M_PTS + j] : 0.f;
                Jacr[t][m] = 0.f; Jaci[t][m] = 0.f;
            }
        }
        float Racr[NK] = {0.f, 0.f, 0.f, 0.f};
        float Raci[NK] = {0.f, 0.f, 0.f, 0.f};

#pragma unroll 1
        for (int o = 0; o < 32; o++) {
#pragma unroll
            for (int t = 0; t < 4; t++) {
                // R3-exact distance form (numerically load-bearing!)
                float dot = fmaf(Rpx, Jpx[t], fmaf(Rpy, Jpy[t], Rpz * Jpz[t]));
                float e   = fmaf(-0.5f, dot, Rr2 + Jr2[t]);   // 0.25*d2
                e = fmaxf(e, 2.5e-13f);
                float th = fsqrt_approx(e);           // 0.5*D
                float sc = rsqrtf(e);                 // 2/D (scale folded in a)
                float s1, c1;
                __sincosf(th, &s1, &c1);
                float tc  = fdouble_alu(c1);
                float g1r = sc * c1,             g1i = sc * s1;
                float g2r = fmaf(tc, g1r, -sc);  float g2i = tc * g1i;
                float g3r = fmaf(tc, g2r, -g1r); float g3i = fmaf(tc, g2i, -g1i);
                float g4r = fmaf(tc, g3r, -g2r); float g4i = fmaf(tc, g3i, -g2i);
                float gr[NK] = {g1r, g2r, g3r, g4r};
                float gi[NK] = {g1i, g2i, g3i, g4i};
#pragma unroll
                for (int m = 0; m < NK; m++) {
                    // j-side: out(j) += G * a(i_rot)
                    Jacr[t][m] = fmaf(gr[m], Rar[m], fmaf(-gi[m], Rai[m], Jacr[t][m]));
                    Jaci[t][m] = fmaf(gr[m], Rai[m], fmaf( gi[m], Rar[m], Jaci[t][m]));
                    // i-side: out(i_rot) += G * a(j)
                    Racr[m] = fmaf(gr[m], Jar[t][m], fmaf(-gi[m], Jai[t][m], Racr[m]));
                    Raci[m] = fmaf(gr[m], Jai[t][m], fmaf( gi[m], Jar[t][m], Raci[m]));
                }
            }
            // rotate i-context (pos + a + acc) by one lane
            Rpx = __shfl_sync(0xffffffffu, Rpx, src);
            Rpy = __shfl_sync(0xffffffffu, Rpy, src);
            Rpz = __shfl_sync(0xffffffffu, Rpz, src);
            Rr2 = __shfl_sync(0xffffffffu, Rr2, src);
#pragma unroll
            for (int m = 0; m < NK; m++) {
                Rar[m]  = __shfl_sync(0xffffffffu, Rar[m],  src);
                Rai[m]  = __shfl_sync(0xffffffffu, Rai[m],  src);
                Racr[m] = __shfl_sync(0xffffffffu, Racr[m], src);
                Raci[m] = __shfl_sync(0xffffffffu, Raci[m], src);
            }
        }
        // 32 rotations -> acc back home. Flush.
#pragma unroll
        for (int m = 0; m < NK; m++) {
            g_ipart[a][sub][lane][2 * m]     = Racr[m];
            g_ipart[a][sub][lane][2 * m + 1] = Raci[m];
        }
#pragma unroll
        for (int t = 0; t < 4; t++) {
            if (valid[t]) {
                int d = 4 * sub + 1 + t;
#pragma unroll
                for (int m = 0; m < NK; m++) {
                    g_jpart[brow[t]][d][lane][2 * m]     = Jacr[t][m];
                    g_jpart[brow[t]][d][lane][2 * m + 1] = Jaci[t][m];
                }
            }
        }
    } else {
        // ---- diagonal tile (a,a): single-side, skip i==j (o starts at 1) ----
        float Jpx = Rpx, Jpy = Rpy, Jpz = Rpz, Jr2 = Rr2;
        float Jar[NK], Jai[NK], Jacr[NK], Jaci[NK];
#pragma unroll
        for (int m = 0; m < NK; m++) {
            Jar[m] = Rar[m]; Jai[m] = Rai[m];
            Jacr[m] = 0.f; Jaci[m] = 0.f;
        }
        (void)Jar; (void)Jai;
#pragma unroll 1
        for (int o = 1; o < 32; o++) {
            // rotate first (skip o=0 self pair)
            Rpx = __shfl_sync(0xffffffffu, Rpx, src);
            Rpy = __shfl_sync(0xffffffffu, Rpy, src);
            Rpz = __shfl_sync(0xffffffffu, Rpz, src);
            Rr2 = __shfl_sync(0xffffffffu, Rr2, src);
#pragma unroll
            for (int m = 0; m < NK; m++) {
                Rar[m] = __shfl_sync(0xffffffffu, Rar[m], src);
                Rai[m] = __shfl_sync(0xffffffffu, Rai[m], src);
            }
            float dot = fmaf(Rpx, Jpx, fmaf(Rpy, Jpy, Rpz * Jpz));
            float e   = fmaf(-0.5f, dot, Rr2 + Jr2);          // 0.25*d2
            e = fmaxf(e, 2.5e-13f);
            float th = fsqrt_approx(e);
            float sc = rsqrtf(e);
            float s1, c1;
            __sincosf(th, &s1, &c1);
            float tc  = fdouble_alu(c1);
            float g1r = sc * c1,             g1i = sc * s1;
            float g2r = fmaf(tc, g1r, -sc);  float g2i = tc * g1i;
            float g3r = fmaf(tc, g2r, -g1r); float g3i = fmaf(tc, g2i, -g1i);
            float g4r = fmaf(tc, g3r, -g2r); float g4i = fmaf(tc, g3i, -g2i);
            float gr[NK] = {g1r, g2r, g3r, g4r};
            float gi[NK] = {g1i, g2i, g3i, g4i};
#pragma unroll
            for (int m = 0; m < NK; m++) {
                Jacr[m] = fmaf(gr[m], Rar[m], fmaf(-gi[m], Rai[m], Jacr[m]));
                Jaci[m] = fmaf(gr[m], Rai[m], fmaf( gi[m], Rar[m], Jaci[m]));
            }
        }
#pragma unroll
        for (int m = 0; m < NK; m++) {
            g_jpart[a][0][lane][2 * m]     = Jacr[m];
            g_jpart[a][0][lane][2 * m + 1] = Jaci[m];
        }
    }
}

// ---------------------------------------------------------------------------
// Deterministic reduction + Born update: p = p0 + sum; a = vw*p.
// One thread per (row, slot); fixed summation order.
// ---------------------------------------------------------------------------
__global__ void k_update() {
    pdl_wait();
    int idx  = blockIdx.x * blockDim.x + threadIdx.x;   // 0 .. 32767
    int slot = idx & 7;
    int r    = idx >> 3;
    int c = r >> 5, l = r & 31;
    float s = 0.f;
#pragma unroll 4
    for (int ch = 0; ch < NCHUNK; ch++) s += g_ipart[c][ch][l][slot];
#pragma unroll 4
    for (int d = 0; d < 64; d++)        s += g_jpart[c][d][l][slot];
    if (c >= 64)                         s += g_jpart[c][64][l][slot];
    int m = slot >> 1, ci = slot & 1;
    int e = m * 2 * M_PTS + ci * M_PTS + r;
    float pv = g_p0[e] + s;
    g_p[e] = pv;
    g_a[e] = g_vw[r] * pv;
}

// ---------------------------------------------------------------------------
// Far-field: one block per observation direction.
// ---------------------------------------------------------------------------
__global__ __launch_bounds__(256) void k_far(const float* __restrict__ V,
                                             const float* __restrict__ obs,
                                             const float* __restrict__ w,
                                             float* __restrict__ out) {
    constexpr int FTPB = 256;
    pdl_wait();
    int d = blockIdx.x;
    int t = threadIdx.x;
    float ox = obs[3 * d], oy = obs[3 * d + 1], oz = obs[3 * d + 2];

    float fr[NK] = {0.f, 0.f, 0.f, 0.f};
    float fi[NK] = {0.f, 0.f, 0.f, 0.f};

    for (int j = t; j < M_PTS; j += FTPB) {
        float q = fmaf(g_px[j], ox, fmaf(g_py[j], oy, g_pz[j] * oz));
        float s1, c1;
        __sincosf(0.5f * q, &s1, &c1);
        float tc = c1 + c1;
        float cm[NK], sm[NK];
        cm[0] = c1;                      sm[0] = s1;
        cm[1] = fmaf(tc, c1, -1.f);      sm[1] = tc * s1;
        cm[2] = fmaf(tc, cm[1], -cm[0]); sm[2] = fmaf(tc, sm[1], -sm[0]);
        cm[3] = fmaf(tc, cm[2], -cm[1]); sm[3] = fmaf(tc, sm[2], -sm[1]);
        float v = V[j], wj = w[j];
#pragma unroll
        for (int m = 0; m < NK; m++) {
            float pr = g_p[m * 2 * M_PTS + j];
            float pi = g_p[m * 2 * M_PTS + M_PTS + j];
            float zr = v * pr, zi = v * pi;
            float ir = fmaf(zr, cm[m],  zi * sm[m]);   // exp(-ikQ)
            float ii = fmaf(zi, cm[m], -zr * sm[m]);
            fr[m] = fmaf(wj, ir, fr[m]);
            fi[m] = fmaf(wj, ii, fi[m]);
        }
    }

#pragma unroll
    for (int off = 16; off; off >>= 1) {
#pragma unroll
        for (int m = 0; m < NK; m++) {
            fr[m] += __shfl_down_sync(0xffffffffu, fr[m], off);
            fi[m] += __shfl_down_sync(0xffffffffu, fi[m], off);
        }
    }
    __shared__ float sred[8][FTPB / 32];
    int lane = t & 31, wid = t >> 5;
    if (lane == 0) {
#pragma unroll
        for (int m = 0; m < NK; m++) {
            sred[2 * m][wid]     = fr[m];
            sred[2 * m + 1][wid] = fi[m];
        }
    }
    __syncthreads();
    if (t < 8) {
        float s = 0.f;
#pragma unroll
        for (int wdx = 0; wdx < FTPB / 32; wdx++) s += sred[t][wdx];
        int m = t >> 1, c = t & 1;
        out[m * NDOBS * 2 + d * 2 + c] = -C_G * s;
    }
}

// ---------------------------------------------------------------------------
template <typename K, typename... Args>
static inline void launch_pdl(K kernel, dim3 grid, dim3 block, Args... args) {
    cudaLaunchConfig_t cfg = {};
    cfg.gridDim = grid;
    cfg.blockDim = block;
    cfg.dynamicSmemBytes = 0;
    cfg.stream = 0;
    cudaLaunchAttribute at[1];
    at[0].id = cudaLaunchAttributeProgrammaticStreamSerialization;
    at[0].val.programmaticStreamSerializationAllowed = 1;
    cfg.attrs = at;
    cfg.numAttrs = 1;
    cudaLaunchKernelEx(&cfg, kernel, args...);
}

extern "C" void kernel_launch(void* const* d_in, const int* in_sizes, int n_in,
                              void* d_out, int out_size) {
    const float* V   = (const float*)d_in[0];   // [4096]
    const float* obs = (const float*)d_in[1];   // [64,3]
    const float* pts = (const float*)d_in[2];   // [4096,3]
    const float* w   = (const float*)d_in[3];   // [4096]
    float* out = (float*)d_out;                 // [4,64,2]

    k_init<<<M_PTS / 256, 256>>>(V, pts, w);
    for (int it = 0; it < N_ITER; it++) {
        launch_pdl(k_acc, dim3(NBLK), dim3(128));
        launch_pdl(k_update, dim3(128), dim3(256));
    }
    launch_pdl(k_far, dim3(NDOBS), dim3(256), V, obs, w, out);
}